// round 1
// baseline (speedup 1.0000x reference)
#include <cuda_runtime.h>
#include <cuda_bf16.h>
#include <math.h>

// Problem constants (fixed shapes for this problem instance)
#define D        1024      // model dim
#define E        8         // num experts
#define MOED     2048      // MOE_DIM
#define TOPK     2
#define MAXROWS  16384     // T * TOPK upper bound (8192*2)

#define BM 64
#define BN 64
#define BK 16

// ---------------- device scratch (static globals: no allocation allowed) ----
__device__ int   g_count[E];
__device__ int   g_offset[E];
__device__ int   g_tokens[E][MAXROWS];
__device__ float g_weights[E][MAXROWS];
// hidden activations, grouped layout; +64 row pad so edge tiles can read OOB rows safely
__device__ float g_hidden[(MAXROWS + 64) * MOED];

// ---------------- init: zero output + counters --------------------------------
__global__ void init_kernel(float* __restrict__ out, int n) {
    int i = blockIdx.x * blockDim.x + threadIdx.x;
    if (i < E) g_count[i] = 0;
    for (; i < n; i += gridDim.x * blockDim.x) out[i] = 0.0f;
}

// ---------------- router: logits, top-2, softmax, bucket dispatch -------------
__global__ void router_kernel(const float* __restrict__ x,
                              const float* __restrict__ router, int T) {
    __shared__ float s_r[D * E];       // 32 KB router weights
    __shared__ float s_logits[32][E];
    int tid = threadIdx.x;             // 256 threads
    for (int i = tid; i < D * E; i += 256) s_r[i] = router[i];
    __syncthreads();

    int tl = tid >> 3;                 // local token 0..31
    int e  = tid & 7;                  // expert 0..7
    int t  = blockIdx.x * 32 + tl;
    float acc = 0.0f;
    if (t < T) {
        const float* xr = x + (size_t)t * D;
        #pragma unroll 8
        for (int k = 0; k < D; k++) acc = fmaf(xr[k], s_r[k * E + e], acc);
    }
    s_logits[tl][e] = acc;
    __syncthreads();

    if (tid < 32) {
        int t2 = blockIdx.x * 32 + tid;
        if (t2 < T) {
            float* L = s_logits[tid];
            int e0 = 0; float l0 = L[0];
            #pragma unroll
            for (int i = 1; i < E; i++) if (L[i] > l0) { l0 = L[i]; e0 = i; }
            int e1 = -1; float l1 = -INFINITY;
            #pragma unroll
            for (int i = 0; i < E; i++) {
                if (i == e0) continue;
                if (L[i] > l1) { l1 = L[i]; e1 = i; }
            }
            float w0 = 1.0f / (1.0f + expf(l1 - l0));   // softmax over 2 (l0 >= l1)
            float w1 = 1.0f - w0;
            int s0 = atomicAdd(&g_count[e0], 1);
            g_tokens[e0][s0]  = t2;
            g_weights[e0][s0] = w0;
            int s1 = atomicAdd(&g_count[e1], 1);
            g_tokens[e1][s1]  = t2;
            g_weights[e1][s1] = w1;
        }
    }
}

// ---------------- prefix offsets ----------------------------------------------
__global__ void offsets_kernel() {
    if (threadIdx.x == 0 && blockIdx.x == 0) {
        int s = 0;
        #pragma unroll
        for (int i = 0; i < E; i++) { g_offset[i] = s; s += g_count[i]; }
    }
}

// ---------------- GEMM1: hidden = silu(X @ W1) * (X @ W3), gathered rows ------
// grid: (MOED/BN, ceil(MAXROWS/BM), E), 256 threads
__global__ void gemm1_kernel(const float* __restrict__ x,
                             const float* __restrict__ w13) {
    int e   = blockIdx.z;
    int cnt = g_count[e];
    int m0  = blockIdx.y * BM;
    if (m0 >= cnt) return;
    int n0  = blockIdx.x * BN;

    __shared__ float As[BK][BM + 1];
    __shared__ float Bg[BK][BN];
    __shared__ float Bu[BK][BN];
    __shared__ int   s_tok[BM];

    int tid = threadIdx.x;
    if (tid < BM) {
        int m = m0 + tid;
        s_tok[tid] = (m < cnt) ? g_tokens[e][m] : 0;
    }
    __syncthreads();

    const float* w13e = w13 + (size_t)e * D * (2 * MOED);
    int tx = tid & 15;   // n quad
    int ty = tid >> 4;   // m quad
    float accg[4][4]; float accu[4][4];
    #pragma unroll
    for (int i = 0; i < 4; i++)
        #pragma unroll
        for (int j = 0; j < 4; j++) { accg[i][j] = 0.0f; accu[i][j] = 0.0f; }

    int a_kk = tid & 15;
    int a_r  = tid >> 4;    // 0..15
    int b_nc = tid & 63;
    int b_kr = tid >> 6;    // 0..3

    for (int k0 = 0; k0 < D; k0 += BK) {
        // load A tile (64 rows x 16 k), transposed into As[k][m]
        #pragma unroll
        for (int i = 0; i < 4; i++) {
            int row = a_r + 16 * i;
            As[a_kk][row] = x[(size_t)s_tok[row] * D + k0 + a_kk];
        }
        // load gate + up B tiles (16 k x 64 n)
        #pragma unroll
        for (int i = 0; i < 4; i++) {
            int kk = b_kr + 4 * i;
            size_t base = (size_t)(k0 + kk) * (2 * MOED) + n0 + b_nc;
            Bg[kk][b_nc] = w13e[base];
            Bu[kk][b_nc] = w13e[base + MOED];
        }
        __syncthreads();

        #pragma unroll
        for (int kk = 0; kk < BK; kk++) {
            float a[4], bg[4], bu[4];
            #pragma unroll
            for (int i = 0; i < 4; i++) a[i]  = As[kk][ty * 4 + i];
            #pragma unroll
            for (int j = 0; j < 4; j++) bg[j] = Bg[kk][tx * 4 + j];
            #pragma unroll
            for (int j = 0; j < 4; j++) bu[j] = Bu[kk][tx * 4 + j];
            #pragma unroll
            for (int i = 0; i < 4; i++)
                #pragma unroll
                for (int j = 0; j < 4; j++) {
                    accg[i][j] = fmaf(a[i], bg[j], accg[i][j]);
                    accu[i][j] = fmaf(a[i], bu[j], accu[i][j]);
                }
        }
        __syncthreads();
    }

    // epilogue: SwiGLU, write hidden (grouped layout)
    int off = g_offset[e];
    #pragma unroll
    for (int i = 0; i < 4; i++) {
        int m = m0 + ty * 4 + i;
        if (m < cnt) {
            float* hrow = g_hidden + (size_t)(off + m) * MOED + n0 + tx * 4;
            #pragma unroll
            for (int j = 0; j < 4; j++) {
                float g = accg[i][j];
                float u = accu[i][j];
                float h = (g / (1.0f + expf(-g))) * u;
                hrow[j] = h;
            }
        }
    }
}

// ---------------- GEMM2: out[t] += w * (hidden @ W2) ---------------------------
// grid: (D/BN, ceil(MAXROWS/BM), E), 256 threads
__global__ void gemm2_kernel(const float* __restrict__ w2,
                             float* __restrict__ out) {
    int e   = blockIdx.z;
    int cnt = g_count[e];
    int m0  = blockIdx.y * BM;
    if (m0 >= cnt) return;
    int n0  = blockIdx.x * BN;

    __shared__ float As[BK][BM + 1];
    __shared__ float Bs[BK][BN];

    int tid = threadIdx.x;
    int tx = tid & 15;
    int ty = tid >> 4;
    float acc[4][4];
    #pragma unroll
    for (int i = 0; i < 4; i++)
        #pragma unroll
        for (int j = 0; j < 4; j++) acc[i][j] = 0.0f;

    const float* w2e = w2 + (size_t)e * MOED * D;
    const float* A   = g_hidden + (size_t)g_offset[e] * MOED;

    int a_kk = tid & 15;
    int a_r  = tid >> 4;
    int b_nc = tid & 63;
    int b_kr = tid >> 6;

    for (int k0 = 0; k0 < MOED; k0 += BK) {
        #pragma unroll
        for (int i = 0; i < 4; i++) {
            int row = a_r + 16 * i;
            // rows beyond cnt read stale-but-finite data; results are masked in epilogue.
            As[a_kk][row] = A[(size_t)(m0 + row) * MOED + k0 + a_kk];
        }
        #pragma unroll
        for (int i = 0; i < 4; i++) {
            int kk = b_kr + 4 * i;
            Bs[kk][b_nc] = w2e[(size_t)(k0 + kk) * D + n0 + b_nc];
        }
        __syncthreads();

        #pragma unroll
        for (int kk = 0; kk < BK; kk++) {
            float a[4], b[4];
            #pragma unroll
            for (int i = 0; i < 4; i++) a[i] = As[kk][ty * 4 + i];
            #pragma unroll
            for (int j = 0; j < 4; j++) b[j] = Bs[kk][tx * 4 + j];
            #pragma unroll
            for (int i = 0; i < 4; i++)
                #pragma unroll
                for (int j = 0; j < 4; j++)
                    acc[i][j] = fmaf(a[i], b[j], acc[i][j]);
        }
        __syncthreads();
    }

    // epilogue: weighted scatter-add to token order
    #pragma unroll
    for (int i = 0; i < 4; i++) {
        int m = m0 + ty * 4 + i;
        if (m < cnt) {
            int   t = g_tokens[e][m];
            float w = g_weights[e][m];
            float* orow = out + (size_t)t * D + n0 + tx * 4;
            #pragma unroll
            for (int j = 0; j < 4; j++)
                atomicAdd(&orow[j], w * acc[i][j]);
        }
    }
}

// ---------------- launch --------------------------------------------------------
extern "C" void kernel_launch(void* const* d_in, const int* in_sizes, int n_in,
                              void* d_out, int out_size) {
    const float* x      = (const float*)d_in[0];
    const float* router = (const float*)d_in[1];
    const float* w13    = (const float*)d_in[2];
    const float* w2     = (const float*)d_in[3];
    float* out = (float*)d_out;

    int T = in_sizes[0] / D;   // 8192 tokens

    init_kernel<<<1024, 256>>>(out, out_size);
    router_kernel<<<(T + 31) / 32, 256>>>(x, router, T);
    offsets_kernel<<<1, 32>>>();

    int mtiles = (T * TOPK + BM - 1) / BM;     // worst case: all rows on one expert
    dim3 g1(MOED / BN, mtiles, E);
    gemm1_kernel<<<g1, 256>>>(x, w13);
    dim3 g2(D / BN, mtiles, E);
    gemm2_kernel<<<g2, 256>>>(w2, out);
}

// round 5
// speedup vs baseline: 1.9735x; 1.9735x over previous
#include <cuda_runtime.h>
#include <cuda_bf16.h>
#include <math.h>
#include <stdint.h>

// ---------------- problem constants ----------------
#define D        1024
#define E        8
#define MOED     2048
#define MAXROWS  16384
#define PADROWS  (MAXROWS + 256)

#define BK       32        // k elems per mainloop iter
#define ARS      80        // A smem row stride (32 bf16 = 64B + 16 pad)
#define BRS      272       // B smem row stride (128 bf16 = 256B + 16 pad)
#define AH_OFF   0
#define AL_OFF   10240
#define BH_OFF   20480
#define BL_OFF   29184
#define SM_BYTES 37888

// ---------------- device scratch (R1-proven footprint) ----------------
__device__ int   g_count[E];
__device__ int   g_offset[E];
__device__ int   g_tokens[E][MAXROWS];
__device__ float g_weights[E][MAXROWS];
__device__ float g_hidden[(size_t)PADROWS * MOED];

// ---------------- helpers ----------------
__device__ __forceinline__ uint32_t smem_u32(const void* p) {
    uint32_t a;
    asm("{ .reg .u64 t; cvta.to.shared.u64 t, %1; cvt.u32.u64 %0, t; }" : "=r"(a) : "l"(p));
    return a;
}
__device__ __forceinline__ void ldsm4(uint32_t* r, uint32_t addr) {
    asm volatile("ldmatrix.sync.aligned.m8n8.x4.shared.b16 {%0,%1,%2,%3}, [%4];"
        : "=r"(r[0]), "=r"(r[1]), "=r"(r[2]), "=r"(r[3]) : "r"(addr));
}
__device__ __forceinline__ void ldsm4t(uint32_t* r, uint32_t addr) {
    asm volatile("ldmatrix.sync.aligned.m8n8.x4.trans.shared.b16 {%0,%1,%2,%3}, [%4];"
        : "=r"(r[0]), "=r"(r[1]), "=r"(r[2]), "=r"(r[3]) : "r"(addr));
}
__device__ __forceinline__ void mma16816(float* c, const uint32_t* a, uint32_t b0, uint32_t b1) {
    asm volatile("mma.sync.aligned.m16n8k16.row.col.f32.bf16.bf16.f32 "
        "{%0,%1,%2,%3}, {%4,%5,%6,%7}, {%8,%9}, {%0,%1,%2,%3};"
        : "+f"(c[0]), "+f"(c[1]), "+f"(c[2]), "+f"(c[3])
        : "r"(a[0]), "r"(a[1]), "r"(a[2]), "r"(a[3]), "r"(b0), "r"(b1));
}
__device__ __forceinline__ uint32_t pack2(float a, float b, uint32_t& lo) {
    __nv_bfloat16 ha = __float2bfloat16(a);
    __nv_bfloat16 hb = __float2bfloat16(b);
    __nv_bfloat16 la = __float2bfloat16(a - __bfloat162float(ha));
    __nv_bfloat16 lb = __float2bfloat16(b - __bfloat162float(hb));
    lo = (uint32_t)__bfloat16_as_ushort(la) | ((uint32_t)__bfloat16_as_ushort(lb) << 16);
    return (uint32_t)__bfloat16_as_ushort(ha) | ((uint32_t)__bfloat16_as_ushort(hb) << 16);
}
__device__ __forceinline__ void cvt8(float4 v0, float4 v1, uint4& hi, uint4& lo) {
    uint32_t l0, l1, l2, l3;
    uint32_t h0 = pack2(v0.x, v0.y, l0);
    uint32_t h1 = pack2(v0.z, v0.w, l1);
    uint32_t h2 = pack2(v1.x, v1.y, l2);
    uint32_t h3 = pack2(v1.z, v1.w, l3);
    hi = make_uint4(h0, h1, h2, h3);
    lo = make_uint4(l0, l1, l2, l3);
}

// ---------------- init (R1-proven) ----------------
__global__ void init_kernel(float* __restrict__ out, int n) {
    int i = blockIdx.x * blockDim.x + threadIdx.x;
    if (i < E) g_count[i] = 0;
    for (; i < n; i += gridDim.x * blockDim.x) out[i] = 0.0f;
}

// ---------------- router (R1-proven, verbatim) ----------------
__global__ void router_kernel(const float* __restrict__ x,
                              const float* __restrict__ router, int T) {
    __shared__ float s_r[D * E];
    __shared__ float s_logits[32][E];
    int tid = threadIdx.x;
    for (int i = tid; i < D * E; i += 256) s_r[i] = router[i];
    __syncthreads();

    int tl = tid >> 3;
    int e  = tid & 7;
    int t  = blockIdx.x * 32 + tl;
    float acc = 0.0f;
    if (t < T) {
        const float* xr = x + (size_t)t * D;
        #pragma unroll 8
        for (int k = 0; k < D; k++) acc = fmaf(xr[k], s_r[k * E + e], acc);
    }
    s_logits[tl][e] = acc;
    __syncthreads();

    if (tid < 32) {
        int t2 = blockIdx.x * 32 + tid;
        if (t2 < T) {
            float* L = s_logits[tid];
            int e0 = 0; float l0 = L[0];
            #pragma unroll
            for (int i = 1; i < E; i++) if (L[i] > l0) { l0 = L[i]; e0 = i; }
            int e1 = -1; float l1 = -INFINITY;
            #pragma unroll
            for (int i = 0; i < E; i++) {
                if (i == e0) continue;
                if (L[i] > l1) { l1 = L[i]; e1 = i; }
            }
            float w0 = 1.0f / (1.0f + expf(l1 - l0));
            float w1 = 1.0f - w0;
            int s0 = atomicAdd(&g_count[e0], 1);
            g_tokens[e0][s0]  = t2;
            g_weights[e0][s0] = w0;
            int s1 = atomicAdd(&g_count[e1], 1);
            g_tokens[e1][s1]  = t2;
            g_weights[e1][s1] = w1;
        }
    }
}

__global__ void offsets_kernel() {
    if (threadIdx.x == 0) {
        int s = 0;
        #pragma unroll
        for (int i = 0; i < E; i++) { g_offset[i] = s; s += g_count[i]; }
    }
}

// ---------------- GEMM1: 128m x (64 gate + 64 up), mma.sync, SwiGLU ----------
__global__ void __launch_bounds__(256) gemm1_kernel(const float* __restrict__ x,
                                                    const float* __restrict__ w13) {
    __shared__ __align__(16) char sm[SM_BYTES];
    __shared__ int s_tok[128];
    int e   = blockIdx.z;
    int cnt = g_count[e];
    int m0  = blockIdx.y * 128;
    if (m0 >= cnt) return;
    int n0  = blockIdx.x * 64;
    int off = g_offset[e];
    int tid = threadIdx.x, wid = tid >> 5, lane = tid & 31;

    if (tid < 128) {
        int m = m0 + tid;
        s_tok[tid] = g_tokens[e][(m < cnt) ? m : (cnt - 1)];
    }
    __syncthreads();

    // staging: A row = tid>>1 (128 rows), 16 floats at k-half (tid&1)*16
    int arow = tid >> 1, akh = tid & 1;
    const float* aptr = x + (size_t)s_tok[arow] * D + akh * 16;
    // B: k-row = tid>>3 (32 rows), 16 n-floats; bc<4 gate, bc>=4 up
    int brow = tid >> 3, bc = tid & 7;
    int ncol = (bc < 4) ? (n0 + bc * 16) : (MOED + n0 + (bc - 4) * 16);
    const float* bptr = w13 + ((size_t)e * D + brow) * (2 * MOED) + ncol;
    uint32_t a_sdst = (uint32_t)(AH_OFF + arow * ARS + akh * 32);
    uint32_t b_sdst = (uint32_t)(BH_OFF + brow * BRS + bc * 32);

    float accg[2][4][4], accu[2][4][4];
    #pragma unroll
    for (int i = 0; i < 2; i++)
        #pragma unroll
        for (int j = 0; j < 4; j++)
            #pragma unroll
            for (int q = 0; q < 4; q++) { accg[i][j][q] = 0.0f; accu[i][j][q] = 0.0f; }

    int wm = wid >> 1, wn = wid & 1;
    int lr = lane & 15, lh16 = (lane >> 4) << 4;
    int btr = ((lane >> 3) & 1) * 8 + (lane & 7);
    uint32_t sb  = smem_u32(sm);
    uint32_t aHb = sb + AH_OFF + (uint32_t)(wm * 32 + lr) * ARS + lh16;
    uint32_t aLb = sb + AL_OFF + (uint32_t)(wm * 32 + lr) * ARS + lh16;
    uint32_t bHb = sb + BH_OFF + (uint32_t)btr * BRS + wn * 64 + lh16;
    uint32_t bLb = sb + BL_OFF + (uint32_t)btr * BRS + wn * 64 + lh16;

    float4 stgA[4], stgB[4];
    #pragma unroll
    for (int q = 0; q < 4; q++) {
        stgA[q] = *reinterpret_cast<const float4*>(aptr + q * 4);
        stgB[q] = *reinterpret_cast<const float4*>(bptr + q * 4);
    }

    const int KT = D / BK;   // 32
    for (int kt = 0; kt < KT; kt++) {
        #pragma unroll
        for (int h = 0; h < 2; h++) {
            uint4 hi, lo;
            cvt8(stgA[2 * h], stgA[2 * h + 1], hi, lo);
            *reinterpret_cast<uint4*>(sm + a_sdst + h * 16) = hi;
            *reinterpret_cast<uint4*>(sm + a_sdst + (AL_OFF - AH_OFF) + h * 16) = lo;
            cvt8(stgB[2 * h], stgB[2 * h + 1], hi, lo);
            *reinterpret_cast<uint4*>(sm + b_sdst + h * 16) = hi;
            *reinterpret_cast<uint4*>(sm + b_sdst + (BL_OFF - BH_OFF) + h * 16) = lo;
        }
        __syncthreads();
        if (kt + 1 < KT) {
            #pragma unroll
            for (int q = 0; q < 4; q++) {
                stgA[q] = *reinterpret_cast<const float4*>(aptr + (kt + 1) * BK + q * 4);
                stgB[q] = *reinterpret_cast<const float4*>(bptr + (size_t)(kt + 1) * BK * (2 * MOED) + q * 4);
            }
        }
        #pragma unroll
        for (int s = 0; s < 2; s++) {
            uint32_t ah[2][4], al[2][4];
            #pragma unroll
            for (int mi = 0; mi < 2; mi++) {
                ldsm4(ah[mi], aHb + mi * 16 * ARS + s * 32);
                ldsm4(al[mi], aLb + mi * 16 * ARS + s * 32);
            }
            #pragma unroll
            for (int half = 0; half < 2; half++) {
                uint32_t gh[4], gl[4], uh[4], ul[4];
                uint32_t boff = (uint32_t)(s * 16 * BRS + half * 32);
                ldsm4t(gh, bHb + boff);
                ldsm4t(gl, bLb + boff);
                ldsm4t(uh, bHb + boff + 128);
                ldsm4t(ul, bLb + boff + 128);
                #pragma unroll
                for (int r = 0; r < 2; r++) {
                    int ni = half * 2 + r;
                    #pragma unroll
                    for (int mi = 0; mi < 2; mi++) {
                        mma16816(accg[mi][ni], ah[mi], gh[2 * r], gh[2 * r + 1]);
                        mma16816(accg[mi][ni], ah[mi], gl[2 * r], gl[2 * r + 1]);
                        mma16816(accg[mi][ni], al[mi], gh[2 * r], gh[2 * r + 1]);
                        mma16816(accu[mi][ni], ah[mi], uh[2 * r], uh[2 * r + 1]);
                        mma16816(accu[mi][ni], ah[mi], ul[2 * r], ul[2 * r + 1]);
                        mma16816(accu[mi][ni], al[mi], uh[2 * r], uh[2 * r + 1]);
                    }
                }
            }
        }
        __syncthreads();
    }

    // epilogue: SwiGLU, store fp32 hidden (grouped layout)
    #pragma unroll
    for (int mi = 0; mi < 2; mi++) {
        #pragma unroll
        for (int rr = 0; rr < 2; rr++) {
            int ml = wm * 32 + mi * 16 + (lane >> 2) + rr * 8;
            if (m0 + ml < cnt) {
                float* hrow = g_hidden + (size_t)(off + m0 + ml) * MOED + n0 + wn * 32;
                #pragma unroll
                for (int ni = 0; ni < 4; ni++) {
                    int nc = ni * 8 + (lane & 3) * 2;
                    float g0 = accg[mi][ni][rr * 2 + 0], g1 = accg[mi][ni][rr * 2 + 1];
                    float u0 = accu[mi][ni][rr * 2 + 0], u1 = accu[mi][ni][rr * 2 + 1];
                    hrow[nc]     = u0 * g0 / (1.0f + __expf(-g0));
                    hrow[nc + 1] = u1 * g1 / (1.0f + __expf(-g1));
                }
            }
        }
    }
}

// ---------------- GEMM2: 128m x 128n, mma.sync, weighted scatter-add ----------
__global__ void __launch_bounds__(256) gemm2_kernel(const float* __restrict__ w2,
                                                    float* __restrict__ out) {
    __shared__ __align__(16) char sm[SM_BYTES];
    int e   = blockIdx.z;
    int cnt = g_count[e];
    int m0  = blockIdx.y * 128;
    if (m0 >= cnt) return;
    int n0  = blockIdx.x * 128;
    int off = g_offset[e];
    int tid = threadIdx.x, wid = tid >> 5, lane = tid & 31;

    int arow = tid >> 1, akh = tid & 1;
    const float* aptr = g_hidden + (size_t)(off + m0 + arow) * MOED + akh * 16;
    int brow = tid >> 3, bc = tid & 7;
    const float* bptr = w2 + ((size_t)e * MOED + brow) * D + n0 + bc * 16;
    uint32_t a_sdst = (uint32_t)(AH_OFF + arow * ARS + akh * 32);
    uint32_t b_sdst = (uint32_t)(BH_OFF + brow * BRS + bc * 32);

    float acc[2][8][4];
    #pragma unroll
    for (int i = 0; i < 2; i++)
        #pragma unroll
        for (int j = 0; j < 8; j++)
            #pragma unroll
            for (int q = 0; q < 4; q++) acc[i][j][q] = 0.0f;

    int wm = wid >> 1, wn = wid & 1;
    int lr = lane & 15, lh16 = (lane >> 4) << 4;
    int btr = ((lane >> 3) & 1) * 8 + (lane & 7);
    uint32_t sb  = smem_u32(sm);
    uint32_t aHb = sb + AH_OFF + (uint32_t)(wm * 32 + lr) * ARS + lh16;
    uint32_t aLb = sb + AL_OFF + (uint32_t)(wm * 32 + lr) * ARS + lh16;
    uint32_t bHb = sb + BH_OFF + (uint32_t)btr * BRS + wn * 128 + lh16;
    uint32_t bLb = sb + BL_OFF + (uint32_t)btr * BRS + wn * 128 + lh16;

    float4 stgA[4], stgB[4];
    #pragma unroll
    for (int q = 0; q < 4; q++) {
        stgA[q] = *reinterpret_cast<const float4*>(aptr + q * 4);
        stgB[q] = *reinterpret_cast<const float4*>(bptr + q * 4);
    }

    const int KT = MOED / BK;   // 64
    for (int kt = 0; kt < KT; kt++) {
        #pragma unroll
        for (int h = 0; h < 2; h++) {
            uint4 hi, lo;
            cvt8(stgA[2 * h], stgA[2 * h + 1], hi, lo);
            *reinterpret_cast<uint4*>(sm + a_sdst + h * 16) = hi;
            *reinterpret_cast<uint4*>(sm + a_sdst + (AL_OFF - AH_OFF) + h * 16) = lo;
            cvt8(stgB[2 * h], stgB[2 * h + 1], hi, lo);
            *reinterpret_cast<uint4*>(sm + b_sdst + h * 16) = hi;
            *reinterpret_cast<uint4*>(sm + b_sdst + (BL_OFF - BH_OFF) + h * 16) = lo;
        }
        __syncthreads();
        if (kt + 1 < KT) {
            #pragma unroll
            for (int q = 0; q < 4; q++) {
                stgA[q] = *reinterpret_cast<const float4*>(aptr + (kt + 1) * BK + q * 4);
                stgB[q] = *reinterpret_cast<const float4*>(bptr + (size_t)(kt + 1) * BK * D + q * 4);
            }
        }
        #pragma unroll
        for (int s = 0; s < 2; s++) {
            uint32_t ah[2][4], al[2][4];
            #pragma unroll
            for (int mi = 0; mi < 2; mi++) {
                ldsm4(ah[mi], aHb + mi * 16 * ARS + s * 32);
                ldsm4(al[mi], aLb + mi * 16 * ARS + s * 32);
            }
            #pragma unroll
            for (int half = 0; half < 4; half++) {
                uint32_t bh[4], bl[4];
                uint32_t boff = (uint32_t)(s * 16 * BRS + half * 32);
                ldsm4t(bh, bHb + boff);
                ldsm4t(bl, bLb + boff);
                #pragma unroll
                for (int r = 0; r < 2; r++) {
                    int ni = half * 2 + r;
                    #pragma unroll
                    for (int mi = 0; mi < 2; mi++) {
                        mma16816(acc[mi][ni], ah[mi], bh[2 * r], bh[2 * r + 1]);
                        mma16816(acc[mi][ni], ah[mi], bl[2 * r], bl[2 * r + 1]);
                        mma16816(acc[mi][ni], al[mi], bh[2 * r], bh[2 * r + 1]);
                    }
                }
            }
        }
        __syncthreads();
    }

    // epilogue: weighted scatter-add (exactly 2 adds per out element -> deterministic)
    #pragma unroll
    for (int mi = 0; mi < 2; mi++) {
        #pragma unroll
        for (int rr = 0; rr < 2; rr++) {
            int ml = wm * 32 + mi * 16 + (lane >> 2) + rr * 8;
            if (m0 + ml < cnt) {
                int   t = g_tokens[e][m0 + ml];
                float w = g_weights[e][m0 + ml];
                float* orow = out + (size_t)t * D;
                #pragma unroll
                for (int ni = 0; ni < 8; ni++) {
                    int nc = n0 + wn * 64 + ni * 8 + (lane & 3) * 2;
                    atomicAdd(orow + nc,     w * acc[mi][ni][rr * 2 + 0]);
                    atomicAdd(orow + nc + 1, w * acc[mi][ni][rr * 2 + 1]);
                }
            }
        }
    }
}

// ---------------- launch ----------------
extern "C" void kernel_launch(void* const* d_in, const int* in_sizes, int n_in,
                              void* d_out, int out_size) {
    const float* x      = (const float*)d_in[0];
    const float* router = (const float*)d_in[1];
    const float* w13    = (const float*)d_in[2];
    const float* w2     = (const float*)d_in[3];
    float* out = (float*)d_out;

    int T = in_sizes[0] / D;   // 8192

    init_kernel<<<1024, 256>>>(out, out_size);
    router_kernel<<<(T + 31) / 32, 256>>>(x, router, T);
    offsets_kernel<<<1, 32>>>();

    int mt = MAXROWS / 128;   // 128
    gemm1_kernel<<<dim3(MOED / 64, mt, E), 256>>>(x, w13);
    gemm2_kernel<<<dim3(D / 128, mt, E), 256>>>(w2, out);
}

// round 7
// speedup vs baseline: 2.1586x; 1.0938x over previous
#include <cuda_runtime.h>
#include <cuda_bf16.h>
#include <math.h>
#include <stdint.h>

// ---------------- problem constants ----------------
#define D        1024
#define E        8
#define MOED     2048
#define MAXROWS  16384
#define PADROWS  (MAXROWS + 256)

#define BK       32        // k elems per mainloop iter
#define ARS      80        // A smem row stride (32 bf16 = 64B + 16 pad)
#define BRS      272       // B smem row stride (128 bf16 = 256B + 16 pad)
#define AH_OFF   0
#define AL_OFF   10240
#define BH_OFF   20480
#define BL_OFF   29184
#define SM_BYTES 37888

// ---------------- device scratch (R5-proven footprint: ~137 MB total) --------
__device__ int   g_count[E];
__device__ int   g_offset[E];
__device__ int   g_tokens[E][MAXROWS];
__device__ float g_weights[E][MAXROWS];
// hidden stored pre-split (same total bytes as the old fp32 buffer)
__device__ __align__(256) __nv_bfloat16 g_hid_hi[(size_t)PADROWS * MOED];
__device__ __align__(256) __nv_bfloat16 g_hid_lo[(size_t)PADROWS * MOED];

// ---------------- helpers ----------------
__device__ __forceinline__ uint32_t smem_u32(const void* p) {
    uint32_t a;
    asm("{ .reg .u64 t; cvta.to.shared.u64 t, %1; cvt.u32.u64 %0, t; }" : "=r"(a) : "l"(p));
    return a;
}
__device__ __forceinline__ void ldsm4(uint32_t* r, uint32_t addr) {
    asm volatile("ldmatrix.sync.aligned.m8n8.x4.shared.b16 {%0,%1,%2,%3}, [%4];"
        : "=r"(r[0]), "=r"(r[1]), "=r"(r[2]), "=r"(r[3]) : "r"(addr));
}
__device__ __forceinline__ void ldsm4t(uint32_t* r, uint32_t addr) {
    asm volatile("ldmatrix.sync.aligned.m8n8.x4.trans.shared.b16 {%0,%1,%2,%3}, [%4];"
        : "=r"(r[0]), "=r"(r[1]), "=r"(r[2]), "=r"(r[3]) : "r"(addr));
}
__device__ __forceinline__ void mma16816(float* c, const uint32_t* a, uint32_t b0, uint32_t b1) {
    asm volatile("mma.sync.aligned.m16n8k16.row.col.f32.bf16.bf16.f32 "
        "{%0,%1,%2,%3}, {%4,%5,%6,%7}, {%8,%9}, {%0,%1,%2,%3};"
        : "+f"(c[0]), "+f"(c[1]), "+f"(c[2]), "+f"(c[3])
        : "r"(a[0]), "r"(a[1]), "r"(a[2]), "r"(a[3]), "r"(b0), "r"(b1));
}
__device__ __forceinline__ uint32_t pack2(float a, float b, uint32_t& lo) {
    __nv_bfloat16 ha = __float2bfloat16(a);
    __nv_bfloat16 hb = __float2bfloat16(b);
    __nv_bfloat16 la = __float2bfloat16(a - __bfloat162float(ha));
    __nv_bfloat16 lb = __float2bfloat16(b - __bfloat162float(hb));
    lo = (uint32_t)__bfloat16_as_ushort(la) | ((uint32_t)__bfloat16_as_ushort(lb) << 16);
    return (uint32_t)__bfloat16_as_ushort(ha) | ((uint32_t)__bfloat16_as_ushort(hb) << 16);
}
__device__ __forceinline__ void cvt8(float4 v0, float4 v1, uint4& hi, uint4& lo) {
    uint32_t l0, l1, l2, l3;
    uint32_t h0 = pack2(v0.x, v0.y, l0);
    uint32_t h1 = pack2(v0.z, v0.w, l1);
    uint32_t h2 = pack2(v1.x, v1.y, l2);
    uint32_t h3 = pack2(v1.z, v1.w, l3);
    hi = make_uint4(h0, h1, h2, h3);
    lo = make_uint4(l0, l1, l2, l3);
}

// ---------------- init ----------------
__global__ void init_kernel(float* __restrict__ out, int n) {
    int i = blockIdx.x * blockDim.x + threadIdx.x;
    if (i < E) g_count[i] = 0;
    for (; i < n; i += gridDim.x * blockDim.x) out[i] = 0.0f;
}

// ---------------- router (proven, verbatim) ----------------
__global__ void router_kernel(const float* __restrict__ x,
                              const float* __restrict__ router, int T) {
    __shared__ float s_r[D * E];
    __shared__ float s_logits[32][E];
    int tid = threadIdx.x;
    for (int i = tid; i < D * E; i += 256) s_r[i] = router[i];
    __syncthreads();

    int tl = tid >> 3;
    int e  = tid & 7;
    int t  = blockIdx.x * 32 + tl;
    float acc = 0.0f;
    if (t < T) {
        const float* xr = x + (size_t)t * D;
        #pragma unroll 8
        for (int k = 0; k < D; k++) acc = fmaf(xr[k], s_r[k * E + e], acc);
    }
    s_logits[tl][e] = acc;
    __syncthreads();

    if (tid < 32) {
        int t2 = blockIdx.x * 32 + tid;
        if (t2 < T) {
            float* L = s_logits[tid];
            int e0 = 0; float l0 = L[0];
            #pragma unroll
            for (int i = 1; i < E; i++) if (L[i] > l0) { l0 = L[i]; e0 = i; }
            int e1 = -1; float l1 = -INFINITY;
            #pragma unroll
            for (int i = 0; i < E; i++) {
                if (i == e0) continue;
                if (L[i] > l1) { l1 = L[i]; e1 = i; }
            }
            float w0 = 1.0f / (1.0f + expf(l1 - l0));
            float w1 = 1.0f - w0;
            int s0 = atomicAdd(&g_count[e0], 1);
            g_tokens[e0][s0]  = t2;
            g_weights[e0][s0] = w0;
            int s1 = atomicAdd(&g_count[e1], 1);
            g_tokens[e1][s1]  = t2;
            g_weights[e1][s1] = w1;
        }
    }
}

__global__ void offsets_kernel() {
    if (threadIdx.x == 0) {
        int s = 0;
        #pragma unroll
        for (int i = 0; i < E; i++) { g_offset[i] = s; s += g_count[i]; }
    }
}

// ---------------- GEMM1: 128m x (64 gate + 64 up), mma.sync, SwiGLU ----------
__global__ void __launch_bounds__(256, 2) gemm1_kernel(const float* __restrict__ x,
                                                       const float* __restrict__ w13) {
    __shared__ __align__(16) char sm[SM_BYTES];
    __shared__ int s_tok[128];
    int e   = blockIdx.z;
    int cnt = g_count[e];
    int m0  = blockIdx.y * 128;
    if (m0 >= cnt) return;
    int n0  = blockIdx.x * 64;
    int off = g_offset[e];
    int tid = threadIdx.x, wid = tid >> 5, lane = tid & 31;

    if (tid < 128) {
        int m = m0 + tid;
        s_tok[tid] = g_tokens[e][(m < cnt) ? m : (cnt - 1)];
    }
    __syncthreads();

    // staging: A row = tid>>1 (128 rows), 16 floats at k-half (tid&1)*16
    int arow = tid >> 1, akh = tid & 1;
    const float* aptr = x + (size_t)s_tok[arow] * D + akh * 16;
    // B: k-row = tid>>3 (32 rows), 16 n-floats; bc<4 gate, bc>=4 up
    int brow = tid >> 3, bc = tid & 7;
    int ncol = (bc < 4) ? (n0 + bc * 16) : (MOED + n0 + (bc - 4) * 16);
    const float* bptr = w13 + ((size_t)e * D + brow) * (2 * MOED) + ncol;
    uint32_t a_sdst = (uint32_t)(AH_OFF + arow * ARS + akh * 32);
    uint32_t b_sdst = (uint32_t)(BH_OFF + brow * BRS + bc * 32);

    float accg[2][4][4], accu[2][4][4];
    #pragma unroll
    for (int i = 0; i < 2; i++)
        #pragma unroll
        for (int j = 0; j < 4; j++)
            #pragma unroll
            for (int q = 0; q < 4; q++) { accg[i][j][q] = 0.0f; accu[i][j][q] = 0.0f; }

    int wm = wid >> 1, wn = wid & 1;
    int lr = lane & 15, lh16 = (lane >> 4) << 4;
    int btr = ((lane >> 3) & 1) * 8 + (lane & 7);
    uint32_t sb  = smem_u32(sm);
    uint32_t aHb = sb + AH_OFF + (uint32_t)(wm * 32 + lr) * ARS + lh16;
    uint32_t aLb = sb + AL_OFF + (uint32_t)(wm * 32 + lr) * ARS + lh16;
    uint32_t bHb = sb + BH_OFF + (uint32_t)btr * BRS + wn * 64 + lh16;
    uint32_t bLb = sb + BL_OFF + (uint32_t)btr * BRS + wn * 64 + lh16;

    float4 stgA[4], stgB[4];
    #pragma unroll
    for (int q = 0; q < 4; q++) {
        stgA[q] = *reinterpret_cast<const float4*>(aptr + q * 4);
        stgB[q] = *reinterpret_cast<const float4*>(bptr + q * 4);
    }

    const int KT = D / BK;   // 32
    for (int kt = 0; kt < KT; kt++) {
        #pragma unroll
        for (int h = 0; h < 2; h++) {
            uint4 hi, lo;
            cvt8(stgA[2 * h], stgA[2 * h + 1], hi, lo);
            *reinterpret_cast<uint4*>(sm + a_sdst + h * 16) = hi;
            *reinterpret_cast<uint4*>(sm + a_sdst + (AL_OFF - AH_OFF) + h * 16) = lo;
            cvt8(stgB[2 * h], stgB[2 * h + 1], hi, lo);
            *reinterpret_cast<uint4*>(sm + b_sdst + h * 16) = hi;
            *reinterpret_cast<uint4*>(sm + b_sdst + (BL_OFF - BH_OFF) + h * 16) = lo;
        }
        __syncthreads();
        if (kt + 1 < KT) {
            #pragma unroll
            for (int q = 0; q < 4; q++) {
                stgA[q] = *reinterpret_cast<const float4*>(aptr + (kt + 1) * BK + q * 4);
                stgB[q] = *reinterpret_cast<const float4*>(bptr + (size_t)(kt + 1) * BK * (2 * MOED) + q * 4);
            }
        }
        #pragma unroll
        for (int s = 0; s < 2; s++) {
            uint32_t ah[2][4], al[2][4];
            #pragma unroll
            for (int mi = 0; mi < 2; mi++) {
                ldsm4(ah[mi], aHb + mi * 16 * ARS + s * 32);
                ldsm4(al[mi], aLb + mi * 16 * ARS + s * 32);
            }
            #pragma unroll
            for (int half = 0; half < 2; half++) {
                uint32_t gh[4], gl[4], uh[4], ul[4];
                uint32_t boff = (uint32_t)(s * 16 * BRS + half * 32);
                ldsm4t(gh, bHb + boff);
                ldsm4t(gl, bLb + boff);
                ldsm4t(uh, bHb + boff + 128);
                ldsm4t(ul, bLb + boff + 128);
                #pragma unroll
                for (int r = 0; r < 2; r++) {
                    int ni = half * 2 + r;
                    #pragma unroll
                    for (int mi = 0; mi < 2; mi++) {
                        mma16816(accg[mi][ni], ah[mi], gh[2 * r], gh[2 * r + 1]);
                        mma16816(accg[mi][ni], ah[mi], gl[2 * r], gl[2 * r + 1]);
                        mma16816(accg[mi][ni], al[mi], gh[2 * r], gh[2 * r + 1]);
                        mma16816(accu[mi][ni], ah[mi], uh[2 * r], uh[2 * r + 1]);
                        mma16816(accu[mi][ni], ah[mi], ul[2 * r], ul[2 * r + 1]);
                        mma16816(accu[mi][ni], al[mi], uh[2 * r], uh[2 * r + 1]);
                    }
                }
            }
        }
        __syncthreads();
    }

    // epilogue: SwiGLU, split in-register, store bf16 hi/lo hidden
    #pragma unroll
    for (int mi = 0; mi < 2; mi++) {
        #pragma unroll
        for (int rr = 0; rr < 2; rr++) {
            int ml = wm * 32 + mi * 16 + (lane >> 2) + rr * 8;
            if (m0 + ml < cnt) {
                size_t rb = (size_t)(off + m0 + ml) * MOED + n0 + wn * 32;
                #pragma unroll
                for (int ni = 0; ni < 4; ni++) {
                    int nc = ni * 8 + (lane & 3) * 2;
                    float g0 = accg[mi][ni][rr * 2 + 0], g1 = accg[mi][ni][rr * 2 + 1];
                    float u0 = accu[mi][ni][rr * 2 + 0], u1 = accu[mi][ni][rr * 2 + 1];
                    float h0 = u0 * g0 / (1.0f + __expf(-g0));
                    float h1 = u1 * g1 / (1.0f + __expf(-g1));
                    uint32_t lo;
                    uint32_t hi = pack2(h0, h1, lo);
                    *reinterpret_cast<uint32_t*>(g_hid_hi + rb + nc) = hi;
                    *reinterpret_cast<uint32_t*>(g_hid_lo + rb + nc) = lo;
                }
            }
        }
    }
}

// ---------------- GEMM2: 128m x 128n, mma.sync, weighted scatter-add ----------
__global__ void __launch_bounds__(256, 2) gemm2_kernel(const float* __restrict__ w2,
                                                       float* __restrict__ out) {
    __shared__ __align__(16) char sm[SM_BYTES];
    int e   = blockIdx.z;
    int cnt = g_count[e];
    int m0  = blockIdx.y * 128;
    if (m0 >= cnt) return;
    int n0  = blockIdx.x * 128;
    int off = g_offset[e];
    int tid = threadIdx.x, wid = tid >> 5, lane = tid & 31;

    // A staging: pre-split bf16 hidden, 16 elems (32B) per thread per iter
    int arow = tid >> 1, akh = tid & 1;
    const __nv_bfloat16* aH = g_hid_hi + (size_t)(off + m0 + arow) * MOED + akh * 16;
    const __nv_bfloat16* aL = g_hid_lo + (size_t)(off + m0 + arow) * MOED + akh * 16;
    int brow = tid >> 3, bc = tid & 7;
    const float* bptr = w2 + ((size_t)e * MOED + brow) * D + n0 + bc * 16;
    uint32_t a_sdst = (uint32_t)(AH_OFF + arow * ARS + akh * 32);
    uint32_t b_sdst = (uint32_t)(BH_OFF + brow * BRS + bc * 32);

    float acc[2][8][4];
    #pragma unroll
    for (int i = 0; i < 2; i++)
        #pragma unroll
        for (int j = 0; j < 8; j++)
            #pragma unroll
            for (int q = 0; q < 4; q++) acc[i][j][q] = 0.0f;

    int wm = wid >> 1, wn = wid & 1;
    int lr = lane & 15, lh16 = (lane >> 4) << 4;
    int btr = ((lane >> 3) & 1) * 8 + (lane & 7);
    uint32_t sb  = smem_u32(sm);
    uint32_t aHb = sb + AH_OFF + (uint32_t)(wm * 32 + lr) * ARS + lh16;
    uint32_t aLb = sb + AL_OFF + (uint32_t)(wm * 32 + lr) * ARS + lh16;
    uint32_t bHb = sb + BH_OFF + (uint32_t)btr * BRS + wn * 128 + lh16;
    uint32_t bLb = sb + BL_OFF + (uint32_t)btr * BRS + wn * 128 + lh16;

    uint4  stgAH[2], stgAL[2];
    float4 stgB[4];
    #pragma unroll
    for (int q = 0; q < 2; q++) {
        stgAH[q] = reinterpret_cast<const uint4*>(aH)[q];
        stgAL[q] = reinterpret_cast<const uint4*>(aL)[q];
    }
    #pragma unroll
    for (int q = 0; q < 4; q++) stgB[q] = *reinterpret_cast<const float4*>(bptr + q * 4);

    const int KT = MOED / BK;   // 64
    for (int kt = 0; kt < KT; kt++) {
        #pragma unroll
        for (int h = 0; h < 2; h++) {
            *reinterpret_cast<uint4*>(sm + a_sdst + h * 16) = stgAH[h];
            *reinterpret_cast<uint4*>(sm + a_sdst + (AL_OFF - AH_OFF) + h * 16) = stgAL[h];
            uint4 hi, lo;
            cvt8(stgB[2 * h], stgB[2 * h + 1], hi, lo);
            *reinterpret_cast<uint4*>(sm + b_sdst + h * 16) = hi;
            *reinterpret_cast<uint4*>(sm + b_sdst + (BL_OFF - BH_OFF) + h * 16) = lo;
        }
        __syncthreads();
        if (kt + 1 < KT) {
            #pragma unroll
            for (int q = 0; q < 2; q++) {
                stgAH[q] = reinterpret_cast<const uint4*>(aH + (kt + 1) * BK)[q];
                stgAL[q] = reinterpret_cast<const uint4*>(aL + (kt + 1) * BK)[q];
            }
            #pragma unroll
            for (int q = 0; q < 4; q++)
                stgB[q] = *reinterpret_cast<const float4*>(bptr + (size_t)(kt + 1) * BK * D + q * 4);
        }
        #pragma unroll
        for (int s = 0; s < 2; s++) {
            uint32_t ah[2][4], al[2][4];
            #pragma unroll
            for (int mi = 0; mi < 2; mi++) {
                ldsm4(ah[mi], aHb + mi * 16 * ARS + s * 32);
                ldsm4(al[mi], aLb + mi * 16 * ARS + s * 32);
            }
            #pragma unroll
            for (int half = 0; half < 4; half++) {
                uint32_t bh[4], bl[4];
                uint32_t boff = (uint32_t)(s * 16 * BRS + half * 32);
                ldsm4t(bh, bHb + boff);
                ldsm4t(bl, bLb + boff);
                #pragma unroll
                for (int r = 0; r < 2; r++) {
                    int ni = half * 2 + r;
                    #pragma unroll
                    for (int mi = 0; mi < 2; mi++) {
                        mma16816(acc[mi][ni], ah[mi], bh[2 * r], bh[2 * r + 1]);
                        mma16816(acc[mi][ni], ah[mi], bl[2 * r], bl[2 * r + 1]);
                        mma16816(acc[mi][ni], al[mi], bh[2 * r], bh[2 * r + 1]);
                    }
                }
            }
        }
        __syncthreads();
    }

    // epilogue: weighted scatter-add (exactly 2 adds per out element -> deterministic)
    #pragma unroll
    for (int mi = 0; mi < 2; mi++) {
        #pragma unroll
        for (int rr = 0; rr < 2; rr++) {
            int ml = wm * 32 + mi * 16 + (lane >> 2) + rr * 8;
            if (m0 + ml < cnt) {
                int   t = g_tokens[e][m0 + ml];
                float w = g_weights[e][m0 + ml];
                float* orow = out + (size_t)t * D;
                #pragma unroll
                for (int ni = 0; ni < 8; ni++) {
                    int nc = n0 + wn * 64 + ni * 8 + (lane & 3) * 2;
                    atomicAdd(orow + nc,     w * acc[mi][ni][rr * 2 + 0]);
                    atomicAdd(orow + nc + 1, w * acc[mi][ni][rr * 2 + 1]);
                }
            }
        }
    }
}

// ---------------- launch ----------------
extern "C" void kernel_launch(void* const* d_in, const int* in_sizes, int n_in,
                              void* d_out, int out_size) {
    const float* x      = (const float*)d_in[0];
    const float* router = (const float*)d_in[1];
    const float* w13    = (const float*)d_in[2];
    const float* w2     = (const float*)d_in[3];
    float* out = (float*)d_out;

    int T = in_sizes[0] / D;   // 8192

    init_kernel<<<1024, 256>>>(out, out_size);
    router_kernel<<<(T + 31) / 32, 256>>>(x, router, T);
    offsets_kernel<<<1, 32>>>();

    int mt = MAXROWS / 128;   // 128
    gemm1_kernel<<<dim3(MOED / 64, mt, E), 256>>>(x, w13);
    gemm2_kernel<<<dim3(D / 128, mt, E), 256>>>(w2, out);
}

// round 8
// speedup vs baseline: 2.8729x; 1.3309x over previous
#include <cuda_runtime.h>
#include <cuda_bf16.h>
#include <math.h>
#include <stdint.h>

// ---------------- problem constants ----------------
#define D        1024
#define E        8
#define MOED     2048
#define MAXROWS  16384
#define PADROWS  (MAXROWS + 256)

#define BK       16        // k elems per pipeline stage
#define ARS      48        // A smem row stride (16 bf16 = 32B + 16 pad)
#define BRS      272       // B smem row stride (128 bf16 = 256B + 16 pad)
#define AH_OFF   0
#define AL_OFF   6144
#define BH_OFF   12288
#define BL_OFF   16640
#define STAGE    20992
#define SM_BYTES (2 * STAGE)   // 41984 <= 48K static limit

// ---------------- device scratch (proven ~137 MB budget) ----------------
__device__ int   g_count[E];
__device__ int   g_offset[E];
__device__ int   g_tokens[E][MAXROWS];
__device__ float g_weights[E][MAXROWS];
__device__ __align__(256) __nv_bfloat16 g_hid_hi[(size_t)PADROWS * MOED];
__device__ __align__(256) __nv_bfloat16 g_hid_lo[(size_t)PADROWS * MOED];

// ---------------- helpers ----------------
__device__ __forceinline__ uint32_t smem_u32(const void* p) {
    uint32_t a;
    asm("{ .reg .u64 t; cvta.to.shared.u64 t, %1; cvt.u32.u64 %0, t; }" : "=r"(a) : "l"(p));
    return a;
}
__device__ __forceinline__ void ldsm4(uint32_t* r, uint32_t addr) {
    asm volatile("ldmatrix.sync.aligned.m8n8.x4.shared.b16 {%0,%1,%2,%3}, [%4];"
        : "=r"(r[0]), "=r"(r[1]), "=r"(r[2]), "=r"(r[3]) : "r"(addr));
}
__device__ __forceinline__ void ldsm4t(uint32_t* r, uint32_t addr) {
    asm volatile("ldmatrix.sync.aligned.m8n8.x4.trans.shared.b16 {%0,%1,%2,%3}, [%4];"
        : "=r"(r[0]), "=r"(r[1]), "=r"(r[2]), "=r"(r[3]) : "r"(addr));
}
__device__ __forceinline__ void mma16816(float* c, const uint32_t* a, uint32_t b0, uint32_t b1) {
    asm volatile("mma.sync.aligned.m16n8k16.row.col.f32.bf16.bf16.f32 "
        "{%0,%1,%2,%3}, {%4,%5,%6,%7}, {%8,%9}, {%0,%1,%2,%3};"
        : "+f"(c[0]), "+f"(c[1]), "+f"(c[2]), "+f"(c[3])
        : "r"(a[0]), "r"(a[1]), "r"(a[2]), "r"(a[3]), "r"(b0), "r"(b1));
}
__device__ __forceinline__ uint32_t pack2(float a, float b, uint32_t& lo) {
    __nv_bfloat16 ha = __float2bfloat16(a);
    __nv_bfloat16 hb = __float2bfloat16(b);
    __nv_bfloat16 la = __float2bfloat16(a - __bfloat162float(ha));
    __nv_bfloat16 lb = __float2bfloat16(b - __bfloat162float(hb));
    lo = (uint32_t)__bfloat16_as_ushort(la) | ((uint32_t)__bfloat16_as_ushort(lb) << 16);
    return (uint32_t)__bfloat16_as_ushort(ha) | ((uint32_t)__bfloat16_as_ushort(hb) << 16);
}
__device__ __forceinline__ void cvt8(float4 v0, float4 v1, uint4& hi, uint4& lo) {
    uint32_t l0, l1, l2, l3;
    uint32_t h0 = pack2(v0.x, v0.y, l0);
    uint32_t h1 = pack2(v0.z, v0.w, l1);
    uint32_t h2 = pack2(v1.x, v1.y, l2);
    uint32_t h3 = pack2(v1.z, v1.w, l3);
    hi = make_uint4(h0, h1, h2, h3);
    lo = make_uint4(l0, l1, l2, l3);
}

// ---------------- init ----------------
__global__ void init_kernel(float* __restrict__ out, int n) {
    int i = blockIdx.x * blockDim.x + threadIdx.x;
    if (i < E) g_count[i] = 0;
    for (; i < n; i += gridDim.x * blockDim.x) out[i] = 0.0f;
}

// ---------------- router (proven, verbatim) ----------------
__global__ void router_kernel(const float* __restrict__ x,
                              const float* __restrict__ router, int T) {
    __shared__ float s_r[D * E];
    __shared__ float s_logits[32][E];
    int tid = threadIdx.x;
    for (int i = tid; i < D * E; i += 256) s_r[i] = router[i];
    __syncthreads();

    int tl = tid >> 3;
    int e  = tid & 7;
    int t  = blockIdx.x * 32 + tl;
    float acc = 0.0f;
    if (t < T) {
        const float* xr = x + (size_t)t * D;
        #pragma unroll 8
        for (int k = 0; k < D; k++) acc = fmaf(xr[k], s_r[k * E + e], acc);
    }
    s_logits[tl][e] = acc;
    __syncthreads();

    if (tid < 32) {
        int t2 = blockIdx.x * 32 + tid;
        if (t2 < T) {
            float* L = s_logits[tid];
            int e0 = 0; float l0 = L[0];
            #pragma unroll
            for (int i = 1; i < E; i++) if (L[i] > l0) { l0 = L[i]; e0 = i; }
            int e1 = -1; float l1 = -INFINITY;
            #pragma unroll
            for (int i = 0; i < E; i++) {
                if (i == e0) continue;
                if (L[i] > l1) { l1 = L[i]; e1 = i; }
            }
            float w0 = 1.0f / (1.0f + expf(l1 - l0));
            float w1 = 1.0f - w0;
            int s0 = atomicAdd(&g_count[e0], 1);
            g_tokens[e0][s0]  = t2;
            g_weights[e0][s0] = w0;
            int s1 = atomicAdd(&g_count[e1], 1);
            g_tokens[e1][s1]  = t2;
            g_weights[e1][s1] = w1;
        }
    }
}

__global__ void offsets_kernel() {
    if (threadIdx.x == 0) {
        int s = 0;
        #pragma unroll
        for (int i = 0; i < E; i++) { g_offset[i] = s; s += g_count[i]; }
    }
}

// ---------------- GEMM1: 128m x (64 gate + 64 up), double-buffered BK=16 ------
__global__ void __launch_bounds__(256, 2) gemm1_kernel(const float* __restrict__ x,
                                                       const float* __restrict__ w13) {
    __shared__ __align__(16) char sm[SM_BYTES];
    __shared__ int s_tok[128];
    int e   = blockIdx.z;
    int cnt = g_count[e];
    int m0  = blockIdx.y * 128;
    if (m0 >= cnt) return;
    int n0  = blockIdx.x * 64;
    int off = g_offset[e];
    int tid = threadIdx.x, wid = tid >> 5, lane = tid & 31;

    if (tid < 128) {
        int m = m0 + tid;
        s_tok[tid] = g_tokens[e][(m < cnt) ? m : (cnt - 1)];
    }
    __syncthreads();

    // A staging: thread -> row tid>>1, k-chunk (tid&1)*8 floats
    int arow = tid >> 1, akh = tid & 1;
    const float* aptr = x + (size_t)s_tok[arow] * D + akh * 8;
    uint32_t a_sdst = (uint32_t)(arow * ARS + akh * 16);
    // B staging: thread -> k-row tid>>4, col chunk (tid&15)*8 floats
    int brow = tid >> 4, bc = tid & 15;
    int c8 = bc * 8;
    int ncol = (c8 < 64) ? (n0 + c8) : (MOED + n0 + (c8 - 64));
    const float* bptr = w13 + ((size_t)e * D + brow) * (2 * MOED) + ncol;
    uint32_t b_sdst = (uint32_t)(BH_OFF + brow * BRS + bc * 16);

    float accg[2][4][4], accu[2][4][4];
    #pragma unroll
    for (int i = 0; i < 2; i++)
        #pragma unroll
        for (int j = 0; j < 4; j++)
            #pragma unroll
            for (int q = 0; q < 4; q++) { accg[i][j][q] = 0.0f; accu[i][j][q] = 0.0f; }

    int wm = wid >> 1, wn = wid & 1;
    int lr = lane & 15, lh16 = (lane >> 4) << 4;
    int btr = ((lane >> 3) & 1) * 8 + (lane & 7);
    uint32_t sb = smem_u32(sm);

    float4 stgA[2], stgB[2];

    // prologue: stage 0 -> buf0, preload stage 1 regs
    stgA[0] = *reinterpret_cast<const float4*>(aptr);
    stgA[1] = *reinterpret_cast<const float4*>(aptr + 4);
    stgB[0] = *reinterpret_cast<const float4*>(bptr);
    stgB[1] = *reinterpret_cast<const float4*>(bptr + 4);
    {
        uint4 hi, lo;
        cvt8(stgA[0], stgA[1], hi, lo);
        *reinterpret_cast<uint4*>(sm + a_sdst) = hi;
        *reinterpret_cast<uint4*>(sm + a_sdst + AL_OFF) = lo;
        cvt8(stgB[0], stgB[1], hi, lo);
        *reinterpret_cast<uint4*>(sm + b_sdst) = hi;
        *reinterpret_cast<uint4*>(sm + b_sdst + (BL_OFF - BH_OFF)) = lo;
    }
    stgA[0] = *reinterpret_cast<const float4*>(aptr + BK);
    stgA[1] = *reinterpret_cast<const float4*>(aptr + BK + 4);
    stgB[0] = *reinterpret_cast<const float4*>(bptr + (size_t)BK * (2 * MOED));
    stgB[1] = *reinterpret_cast<const float4*>(bptr + (size_t)BK * (2 * MOED) + 4);
    __syncthreads();

    const int KT = D / BK;   // 64
    for (int kt = 0; kt < KT; kt++) {
        int nbuf = (kt + 1) & 1;
        if (kt + 1 < KT) {
            uint4 hi, lo;
            cvt8(stgA[0], stgA[1], hi, lo);
            *reinterpret_cast<uint4*>(sm + nbuf * STAGE + a_sdst) = hi;
            *reinterpret_cast<uint4*>(sm + nbuf * STAGE + a_sdst + AL_OFF) = lo;
            cvt8(stgB[0], stgB[1], hi, lo);
            *reinterpret_cast<uint4*>(sm + nbuf * STAGE + b_sdst) = hi;
            *reinterpret_cast<uint4*>(sm + nbuf * STAGE + b_sdst + (BL_OFF - BH_OFF)) = lo;
        }
        if (kt + 2 < KT) {
            stgA[0] = *reinterpret_cast<const float4*>(aptr + (kt + 2) * BK);
            stgA[1] = *reinterpret_cast<const float4*>(aptr + (kt + 2) * BK + 4);
            stgB[0] = *reinterpret_cast<const float4*>(bptr + (size_t)(kt + 2) * BK * (2 * MOED));
            stgB[1] = *reinterpret_cast<const float4*>(bptr + (size_t)(kt + 2) * BK * (2 * MOED) + 4);
        }

        uint32_t bb = sb + (kt & 1) * STAGE;
        uint32_t aH = bb + (uint32_t)(wm * 32 + lr) * ARS + lh16;
        uint32_t aL = aH + AL_OFF;
        uint32_t bH = bb + BH_OFF + (uint32_t)btr * BRS + wn * 64 + lh16;
        uint32_t bL = bH + (BL_OFF - BH_OFF);

        uint32_t ah[2][4], al[2][4];
        #pragma unroll
        for (int mi = 0; mi < 2; mi++) {
            ldsm4(ah[mi], aH + mi * (16 * ARS));
            ldsm4(al[mi], aL + mi * (16 * ARS));
        }
        #pragma unroll
        for (int half = 0; half < 2; half++) {
            uint32_t gh[4], gl[4], uh[4], ul[4];
            uint32_t boff = (uint32_t)(half * 32);
            ldsm4t(gh, bH + boff);
            ldsm4t(gl, bL + boff);
            ldsm4t(uh, bH + boff + 128);
            ldsm4t(ul, bL + boff + 128);
            #pragma unroll
            for (int r = 0; r < 2; r++) {
                int ni = half * 2 + r;
                #pragma unroll
                for (int mi = 0; mi < 2; mi++) {
                    mma16816(accg[mi][ni], ah[mi], gh[2 * r], gh[2 * r + 1]);
                    mma16816(accg[mi][ni], ah[mi], gl[2 * r], gl[2 * r + 1]);
                    mma16816(accg[mi][ni], al[mi], gh[2 * r], gh[2 * r + 1]);
                    mma16816(accu[mi][ni], ah[mi], uh[2 * r], uh[2 * r + 1]);
                    mma16816(accu[mi][ni], ah[mi], ul[2 * r], ul[2 * r + 1]);
                    mma16816(accu[mi][ni], al[mi], uh[2 * r], uh[2 * r + 1]);
                }
            }
        }
        __syncthreads();
    }

    // epilogue: SwiGLU, split in-register, store bf16 hi/lo hidden
    #pragma unroll
    for (int mi = 0; mi < 2; mi++) {
        #pragma unroll
        for (int rr = 0; rr < 2; rr++) {
            int ml = wm * 32 + mi * 16 + (lane >> 2) + rr * 8;
            if (m0 + ml < cnt) {
                size_t rb = (size_t)(off + m0 + ml) * MOED + n0 + wn * 32;
                #pragma unroll
                for (int ni = 0; ni < 4; ni++) {
                    int nc = ni * 8 + (lane & 3) * 2;
                    float g0 = accg[mi][ni][rr * 2 + 0], g1 = accg[mi][ni][rr * 2 + 1];
                    float u0 = accu[mi][ni][rr * 2 + 0], u1 = accu[mi][ni][rr * 2 + 1];
                    float h0 = u0 * g0 / (1.0f + __expf(-g0));
                    float h1 = u1 * g1 / (1.0f + __expf(-g1));
                    uint32_t lo;
                    uint32_t hi = pack2(h0, h1, lo);
                    *reinterpret_cast<uint32_t*>(g_hid_hi + rb + nc) = hi;
                    *reinterpret_cast<uint32_t*>(g_hid_lo + rb + nc) = lo;
                }
            }
        }
    }
}

// ---------------- GEMM2: 128m x 128n, double-buffered BK=16 -------------------
__global__ void __launch_bounds__(256, 2) gemm2_kernel(const float* __restrict__ w2,
                                                       float* __restrict__ out) {
    __shared__ __align__(16) char sm[SM_BYTES];
    int e   = blockIdx.z;
    int cnt = g_count[e];
    int m0  = blockIdx.y * 128;
    if (m0 >= cnt) return;
    int n0  = blockIdx.x * 128;
    int off = g_offset[e];
    int tid = threadIdx.x, wid = tid >> 5, lane = tid & 31;

    // A staging: bf16 pre-split hidden; 8 elems (16B) hi + lo per thread
    int arow = tid >> 1, akh = tid & 1;
    const __nv_bfloat16* aH_src = g_hid_hi + (size_t)(off + m0 + arow) * MOED + akh * 8;
    const __nv_bfloat16* aL_src = g_hid_lo + (size_t)(off + m0 + arow) * MOED + akh * 8;
    uint32_t a_sdst = (uint32_t)(arow * ARS + akh * 16);
    int brow = tid >> 4, bc = tid & 15;
    const float* bptr = w2 + ((size_t)e * MOED + brow) * D + n0 + bc * 8;
    uint32_t b_sdst = (uint32_t)(BH_OFF + brow * BRS + bc * 16);

    float acc[2][8][4];
    #pragma unroll
    for (int i = 0; i < 2; i++)
        #pragma unroll
        for (int j = 0; j < 8; j++)
            #pragma unroll
            for (int q = 0; q < 4; q++) acc[i][j][q] = 0.0f;

    int wm = wid >> 1, wn = wid & 1;
    int lr = lane & 15, lh16 = (lane >> 4) << 4;
    int btr = ((lane >> 3) & 1) * 8 + (lane & 7);
    uint32_t sb = smem_u32(sm);

    uint4 stgAH, stgAL;
    float4 stgB[2];

    stgAH = *reinterpret_cast<const uint4*>(aH_src);
    stgAL = *reinterpret_cast<const uint4*>(aL_src);
    stgB[0] = *reinterpret_cast<const float4*>(bptr);
    stgB[1] = *reinterpret_cast<const float4*>(bptr + 4);
    {
        *reinterpret_cast<uint4*>(sm + a_sdst) = stgAH;
        *reinterpret_cast<uint4*>(sm + a_sdst + AL_OFF) = stgAL;
        uint4 hi, lo;
        cvt8(stgB[0], stgB[1], hi, lo);
        *reinterpret_cast<uint4*>(sm + b_sdst) = hi;
        *reinterpret_cast<uint4*>(sm + b_sdst + (BL_OFF - BH_OFF)) = lo;
    }
    stgAH = *reinterpret_cast<const uint4*>(aH_src + BK);
    stgAL = *reinterpret_cast<const uint4*>(aL_src + BK);
    stgB[0] = *reinterpret_cast<const float4*>(bptr + (size_t)BK * D);
    stgB[1] = *reinterpret_cast<const float4*>(bptr + (size_t)BK * D + 4);
    __syncthreads();

    const int KT = MOED / BK;   // 128
    for (int kt = 0; kt < KT; kt++) {
        int nbuf = (kt + 1) & 1;
        if (kt + 1 < KT) {
            *reinterpret_cast<uint4*>(sm + nbuf * STAGE + a_sdst) = stgAH;
            *reinterpret_cast<uint4*>(sm + nbuf * STAGE + a_sdst + AL_OFF) = stgAL;
            uint4 hi, lo;
            cvt8(stgB[0], stgB[1], hi, lo);
            *reinterpret_cast<uint4*>(sm + nbuf * STAGE + b_sdst) = hi;
            *reinterpret_cast<uint4*>(sm + nbuf * STAGE + b_sdst + (BL_OFF - BH_OFF)) = lo;
        }
        if (kt + 2 < KT) {
            stgAH = *reinterpret_cast<const uint4*>(aH_src + (kt + 2) * BK);
            stgAL = *reinterpret_cast<const uint4*>(aL_src + (kt + 2) * BK);
            stgB[0] = *reinterpret_cast<const float4*>(bptr + (size_t)(kt + 2) * BK * D);
            stgB[1] = *reinterpret_cast<const float4*>(bptr + (size_t)(kt + 2) * BK * D + 4);
        }

        uint32_t bb = sb + (kt & 1) * STAGE;
        uint32_t aH = bb + (uint32_t)(wm * 32 + lr) * ARS + lh16;
        uint32_t aL = aH + AL_OFF;
        uint32_t bH = bb + BH_OFF + (uint32_t)btr * BRS + wn * 128 + lh16;
        uint32_t bL = bH + (BL_OFF - BH_OFF);

        uint32_t ah[2][4], al[2][4];
        #pragma unroll
        for (int mi = 0; mi < 2; mi++) {
            ldsm4(ah[mi], aH + mi * (16 * ARS));
            ldsm4(al[mi], aL + mi * (16 * ARS));
        }
        #pragma unroll
        for (int half = 0; half < 4; half++) {
            uint32_t bh[4], bl[4];
            uint32_t boff = (uint32_t)(half * 32);
            ldsm4t(bh, bH + boff);
            ldsm4t(bl, bL + boff);
            #pragma unroll
            for (int r = 0; r < 2; r++) {
                int ni = half * 2 + r;
                #pragma unroll
                for (int mi = 0; mi < 2; mi++) {
                    mma16816(acc[mi][ni], ah[mi], bh[2 * r], bh[2 * r + 1]);
                    mma16816(acc[mi][ni], ah[mi], bl[2 * r], bl[2 * r + 1]);
                    mma16816(acc[mi][ni], al[mi], bh[2 * r], bh[2 * r + 1]);
                }
            }
        }
        __syncthreads();
    }

    // epilogue: weighted scatter-add (exactly 2 adds per out element)
    #pragma unroll
    for (int mi = 0; mi < 2; mi++) {
        #pragma unroll
        for (int rr = 0; rr < 2; rr++) {
            int ml = wm * 32 + mi * 16 + (lane >> 2) + rr * 8;
            if (m0 + ml < cnt) {
                int   t = g_tokens[e][m0 + ml];
                float w = g_weights[e][m0 + ml];
                float* orow = out + (size_t)t * D;
                #pragma unroll
                for (int ni = 0; ni < 8; ni++) {
                    int nc = n0 + wn * 64 + ni * 8 + (lane & 3) * 2;
                    atomicAdd(orow + nc,     w * acc[mi][ni][rr * 2 + 0]);
                    atomicAdd(orow + nc + 1, w * acc[mi][ni][rr * 2 + 1]);
                }
            }
        }
    }
}

// ---------------- launch ----------------
extern "C" void kernel_launch(void* const* d_in, const int* in_sizes, int n_in,
                              void* d_out, int out_size) {
    const float* x      = (const float*)d_in[0];
    const float* router = (const float*)d_in[1];
    const float* w13    = (const float*)d_in[2];
    const float* w2     = (const float*)d_in[3];
    float* out = (float*)d_out;

    int T = in_sizes[0] / D;   // 8192

    init_kernel<<<1024, 256>>>(out, out_size);
    router_kernel<<<(T + 31) / 32, 256>>>(x, router, T);
    offsets_kernel<<<1, 32>>>();

    int mt = MAXROWS / 128;   // 128
    gemm1_kernel<<<dim3(MOED / 64, mt, E), 256>>>(x, w13);
    gemm2_kernel<<<dim3(D / 128, mt, E), 256>>>(w2, out);
}